// round 12
// baseline (speedup 1.0000x reference)
#include <cuda_runtime.h>
#include <cstdint>

#define BATCH 8
#define C     192
#define CQ    32
#define NPIX  16384
#define SUB   64
#define NSUBT 4
#define TILE  (SUB*NSUBT)     // 256
#define NPARTS (NPIX/TILE)    // 64

typedef unsigned long long u64;

// ---------------- deterministic scratch ----------------
__device__ float g_part_kx  [BATCH*NPARTS*CQ*C];
__device__ float g_part_xsum[BATCH*NPARTS*C];
__device__ float g_part_ksum[BATCH*NPARTS*CQ];
__device__ float g_kx  [BATCH*CQ*C];
__device__ float g_xsum[BATCH*C];
__device__ float g_ksum[BATCH*CQ];
__device__ float g_mat [BATCH*CQ*C];
__device__ float g_vsum[BATCH*C];
__device__ float g_qn  [BATCH*CQ*NPIX];   // 16.8 MB: normalized Q

// ---------------- packed f32x2 helpers ----------------
__device__ __forceinline__ u64 pack2dup(float x) {
    u64 r; asm("mov.b64 %0, {%1, %1};" : "=l"(r) : "f"(x)); return r;
}
__device__ __forceinline__ u64 pack2(float a, float b) {
    u64 r; asm("mov.b64 %0, {%1, %2};" : "=l"(r) : "f"(a), "f"(b)); return r;
}
__device__ __forceinline__ void unpack2(u64 v, float& lo, float& hi) {
    asm("mov.b64 {%0, %1}, %2;" : "=f"(lo), "=f"(hi) : "l"(v));
}
__device__ __forceinline__ u64 ffma2(u64 a, u64 b, u64 c) {
    u64 d; asm("fma.rn.f32x2 %0, %1, %2, %3;" : "=l"(d) : "l"(a), "l"(b), "l"(c));
    return d;
}
__device__ __forceinline__ u64 fmul2(u64 a, u64 b) {
    u64 d; asm("mul.rn.f32x2 %0, %1, %2;" : "=l"(d) : "l"(a), "l"(b)); return d;
}
__device__ __forceinline__ u64 fadd2(u64 a, u64 b) {
    u64 d; asm("add.rn.f32x2 %0, %1, %2;" : "=l"(d) : "l"(a), "l"(b)); return d;
}

// ---------------- smem layout (pass1, float offsets) ----------------
#define P1_BUF0   0        // x1 [192][64] then xt [64][194] -> 12416
#define P1_WK     12416    // [32][196] = 6272
#define P1_WQ     18688    // [32][196] = 6272
#define P1_KN     24960    // [32][64]  = 2048
#define P1_KSQ    27008    // [8][64]   = 512
#define P1_QSQ    27520    // [8][64]   = 512
#define P1_INVN   28032    // [64]
#define P1_INVQ   28096    // [64]
#define P1_WKP    28160    // [32]
#define P1_KSUML  28192    // [32]
#define P1_TOT    28224
#define SMEM1_BYTES (P1_TOT*4)   // 112896 B; 2 CTAs = 225.8 KB <= 228 KB

// =============================================================================
// Pass 1: K-proj (lower half) + Q-proj (upper half) in parallel;
//         Kn, KX = Kn·x^T, ksum, xsum; Qn -> g_qn
// =============================================================================
__global__ __launch_bounds__(256, 2)
void pass1_kernel(const float* __restrict__ x, const float* __restrict__ x1,
                  const float* __restrict__ Wk, const float* __restrict__ bk,
                  const float* __restrict__ Wq, const float* __restrict__ bq)
{
    extern __shared__ float sm[];
    float* buf0  = sm + P1_BUF0;
    float* wk    = sm + P1_WK;
    float* wq    = sm + P1_WQ;
    float* kn    = sm + P1_KN;
    float* ksq   = sm + P1_KSQ;
    float* qsq   = sm + P1_QSQ;
    float* invn  = sm + P1_INVN;
    float* invq  = sm + P1_INVQ;
    float* wkp   = sm + P1_WKP;
    float* ksuml = sm + P1_KSUML;

    const int tid  = threadIdx.x;
    const int lane = tid & 31;
    const int wgrp = tid >> 5;
    const int b    = blockIdx.y;
    const int part = blockIdx.x;
    const int pl   = 2 * lane;
    const int ph   = tid >> 7;          // 0 = K half, 1 = Q half
    const int u    = tid & 127;
    const int mg   = u >> 4;            // m-group (4 m)
    const int qd   = 4 * (u & 15);      // px quad

    // stage both weight matrices, stride 196 (16B-aligned rows)
#pragma unroll
    for (int i = 0; i < 24; i++) {
        int idx = tid + 256 * i;
        int m = idx / 192, k = idx - m * 192;
        wk[m * 196 + k] = Wk[idx];
        wq[m * 196 + k] = Wq[idx];
    }
    if (tid < 32) ksuml[tid] = 0.f;

    float br[4];
#pragma unroll
    for (int mi = 0; mi < 4; mi++)
        br[mi] = ph ? bq[mg * 4 + mi] : bk[mg * 4 + mi];
    const float* wsel = ph ? wq : wk;
    float* sqdst = ph ? qsq : ksq;

    u64 macc[4][3];
#pragma unroll
    for (int i = 0; i < 4; i++)
#pragma unroll
        for (int j = 0; j < 3; j++) macc[i][j] = 0ull;
    u64 xacc = 0ull;

    const float* x1b = x1 + (size_t)b * C * NPIX;
    const float* xb  = x  + (size_t)b * C * NPIX;
    float* qnb = g_qn + (size_t)b * CQ * NPIX;

    for (int s = 0; s < NSUBT; s++) {
        const int n0 = part * TILE + s * SUB;
        __syncthreads();   // A: buf0/kn reuse guard

        // ---- stage x1 -> buf0[c][t] stride 64 (all threads) ----
#pragma unroll
        for (int i = 0; i < 12; i++) {
            int idx = tid + 256 * i;
            int c = idx >> 4, q = idx & 15;
            *(float4*)&buf0[c * 64 + 4 * q] =
                *(const float4*)&x1b[(size_t)c * NPIX + n0 + 4 * q];
        }
        __syncthreads();   // B

        // ---- projection (K on lower half, Q on upper half) ----
        u64 acc[4][2];
#pragma unroll
        for (int mi = 0; mi < 4; mi++) {
            u64 bb = pack2dup(br[mi]);
            acc[mi][0] = bb; acc[mi][1] = bb;
        }
#pragma unroll 3
        for (int k = 0; k < C; k += 4) {
            ulonglong2 xA = *(const ulonglong2*)&buf0[k * 64 + qd];
            ulonglong2 xC = *(const ulonglong2*)&buf0[(k + 1) * 64 + qd];
            ulonglong2 xE = *(const ulonglong2*)&buf0[(k + 2) * 64 + qd];
            ulonglong2 xG = *(const ulonglong2*)&buf0[(k + 3) * 64 + qd];
#pragma unroll
            for (int mi = 0; mi < 4; mi++) {
                float4 w = *(const float4*)&wsel[(mg * 4 + mi) * 196 + k];
                u64 w0 = pack2dup(w.x), w1 = pack2dup(w.y);
                u64 w2 = pack2dup(w.z), w3 = pack2dup(w.w);
                acc[mi][0] = ffma2(xA.x, w0, acc[mi][0]);
                acc[mi][1] = ffma2(xA.y, w0, acc[mi][1]);
                acc[mi][0] = ffma2(xC.x, w1, acc[mi][0]);
                acc[mi][1] = ffma2(xC.y, w1, acc[mi][1]);
                acc[mi][0] = ffma2(xE.x, w2, acc[mi][0]);
                acc[mi][1] = ffma2(xE.y, w2, acc[mi][1]);
                acc[mi][0] = ffma2(xG.x, w3, acc[mi][0]);
                acc[mi][1] = ffma2(xG.y, w3, acc[mi][1]);
            }
        }
        {
            u64 sq0 = fmul2(acc[0][0], acc[0][0]);
            u64 sq1 = fmul2(acc[0][1], acc[0][1]);
#pragma unroll
            for (int mi = 1; mi < 4; mi++) {
                sq0 = ffma2(acc[mi][0], acc[mi][0], sq0);
                sq1 = ffma2(acc[mi][1], acc[mi][1], sq1);
            }
            *(u64*)&sqdst[mg * 64 + qd]     = sq0;
            *(u64*)&sqdst[mg * 64 + qd + 2] = sq1;
        }
        __syncthreads();   // C: proj reads done, ksq+qsq ready

        if (tid < 64) {
            float tot = 0.f;
#pragma unroll
            for (int g = 0; g < 8; g++) tot += ksq[g * 64 + tid];
            invn[tid] = rsqrtf(tot);
        } else if (tid < 128) {
            const int t = tid - 64;
            float tot = 0.f;
#pragma unroll
            for (int g = 0; g < 8; g++) tot += qsq[g * 64 + t];
            invq[t] = rsqrtf(tot);
        }
        // ---- stage x transposed -> buf0 = xt[t][194] (all threads) ----
#pragma unroll
        for (int i = 0; i < 24; i++) {
            int c = (tid >> 5) + 8 * i;
            float2 v = *(const float2*)&xb[(size_t)c * NPIX + n0 + pl];
            buf0[pl * 194 + c]       = v.x;
            buf0[(pl + 1) * 194 + c] = v.y;
        }
        __syncthreads();   // D: invn/invq + xt ready

        if (ph == 0) {
            // ---- kn = K*inv (float4 store), ksum via 16-lane shfl ----
            float4 iv = *(const float4*)&invn[qd];
            u64 iv0 = pack2(iv.x, iv.y), iv1 = pack2(iv.z, iv.w);
            float ksump[4];
#pragma unroll
            for (int mi = 0; mi < 4; mi++) {
                u64 k0 = fmul2(acc[mi][0], iv0);
                u64 k1 = fmul2(acc[mi][1], iv1);
                float a0, a1, a2, a3;
                unpack2(k0, a0, a1); unpack2(k1, a2, a3);
                *(float4*)&kn[(mg * 4 + mi) * 64 + qd] =
                    make_float4(a0, a1, a2, a3);
                ksump[mi] = (a0 + a1) + (a2 + a3);
            }
#pragma unroll
            for (int off = 8; off; off >>= 1)
#pragma unroll
                for (int mi = 0; mi < 4; mi++)
                    ksump[mi] += __shfl_down_sync(0xffffffffu, ksump[mi], off, 16);
            if ((u & 15) == 0)
#pragma unroll
                for (int mi = 0; mi < 4; mi++) wkp[mg * 4 + mi] = ksump[mi];
        } else {
            // ---- qn = Q*invq -> g_qn (STG.128 per m) ----
            float4 iv = *(const float4*)&invq[qd];
            u64 iv0 = pack2(iv.x, iv.y), iv1 = pack2(iv.z, iv.w);
#pragma unroll
            for (int mi = 0; mi < 4; mi++) {
                u64 q0 = fmul2(acc[mi][0], iv0);
                u64 q1 = fmul2(acc[mi][1], iv1);
                float a0, a1, a2, a3;
                unpack2(q0, a0, a1); unpack2(q1, a2, a3);
                *(float4*)&qnb[(size_t)(mg * 4 + mi) * NPIX + n0 + qd] =
                    make_float4(a0, a1, a2, a3);
            }
        }
        __syncthreads();   // E: kn + wkp ready

        if (tid < 32) ksuml[tid] += wkp[tid];

        // ---- xsum partial ----
        if (tid < 96) {
            u64 sv = 0ull;
#pragma unroll 8
            for (int t = 0; t < SUB; t++)
                sv = fadd2(sv, *(const u64*)&buf0[t * 194 + 2 * tid]);
            xacc = fadd2(xacc, sv);
        }

        // ---- KX += kn·x^T (t-block-4, broadcast kn LDS.128) ----
#pragma unroll 4
        for (int tb = 0; tb < 16; tb++) {
            const int t0 = 4 * tb;
            float4 kd[4];
#pragma unroll
            for (int i = 0; i < 4; i++)
                kd[i] = *(const float4*)&kn[(wgrp + 8 * i) * 64 + t0];
#pragma unroll
            for (int tt = 0; tt < 4; tt++) {
                u64 x2[3];
#pragma unroll
                for (int j = 0; j < 3; j++)
                    x2[j] = *(const u64*)&buf0[(t0 + tt) * 194 + pl + 64 * j];
                const float* kf0 = (const float*)&kd[0];
                const float* kf1 = (const float*)&kd[1];
                const float* kf2 = (const float*)&kd[2];
                const float* kf3 = (const float*)&kd[3];
                u64 kd0 = pack2dup(kf0[tt]);
                u64 kd1 = pack2dup(kf1[tt]);
                u64 kd2 = pack2dup(kf2[tt]);
                u64 kd3 = pack2dup(kf3[tt]);
#pragma unroll
                for (int j = 0; j < 3; j++) {
                    macc[0][j] = ffma2(kd0, x2[j], macc[0][j]);
                    macc[1][j] = ffma2(kd1, x2[j], macc[1][j]);
                    macc[2][j] = ffma2(kd2, x2[j], macc[2][j]);
                    macc[3][j] = ffma2(kd3, x2[j], macc[3][j]);
                }
            }
        }
    }

    __syncthreads();
    float* pm = g_part_kx + ((size_t)b * NPARTS + part) * CQ * C;
#pragma unroll
    for (int i = 0; i < 4; i++)
#pragma unroll
        for (int j = 0; j < 3; j++)
            *(u64*)&pm[(wgrp + 8 * i) * C + pl + 64 * j] = macc[i][j];
    if (tid < 96) {
        float lo, hi; unpack2(xacc, lo, hi);
        float* px = g_part_xsum + ((size_t)b * NPARTS + part) * C;
        px[2 * tid] = lo; px[2 * tid + 1] = hi;
    }
    if (tid < 32) g_part_ksum[((size_t)b * NPARTS + part) * CQ + tid] = ksuml[tid];
}

// =============================================================================
// mid1: reduce partials (fixed order, float4)
// =============================================================================
__global__ void mid1_kernel()
{
    const int MAT4 = BATCH * CQ * C / 4;
    const int XS4  = BATCH * C / 4;
    const int KS4  = BATCH * CQ / 4;
    int idx = blockIdx.x * blockDim.x + threadIdx.x;
    if (idx < MAT4) {
        int i4 = idx * 4;
        int bb = i4 / (CQ * C), r = i4 % (CQ * C);
        const float* p = g_part_kx + (size_t)bb * NPARTS * CQ * C + r;
        float4 a = make_float4(0.f, 0.f, 0.f, 0.f);
#pragma unroll 8
        for (int q = 0; q < NPARTS; q++) {
            float4 v = *(const float4*)&p[(size_t)q * CQ * C];
            a.x += v.x; a.y += v.y; a.z += v.z; a.w += v.w;
        }
        *(float4*)&g_kx[i4] = a;
    } else if (idx < MAT4 + XS4) {
        int i4 = (idx - MAT4) * 4;
        int bb = i4 / C, r = i4 % C;
        const float* p = g_part_xsum + (size_t)bb * NPARTS * C + r;
        float4 a = make_float4(0.f, 0.f, 0.f, 0.f);
#pragma unroll 8
        for (int q = 0; q < NPARTS; q++) {
            float4 v = *(const float4*)&p[q * C];
            a.x += v.x; a.y += v.y; a.z += v.z; a.w += v.w;
        }
        *(float4*)&g_xsum[i4] = a;
    } else if (idx < MAT4 + XS4 + KS4) {
        int i4 = (idx - MAT4 - XS4) * 4;
        int bb = i4 / CQ, r = i4 % CQ;
        const float* p = g_part_ksum + (size_t)bb * NPARTS * CQ + r;
        float4 a = make_float4(0.f, 0.f, 0.f, 0.f);
#pragma unroll 8
        for (int q = 0; q < NPARTS; q++) {
            float4 v = *(const float4*)&p[q * CQ];
            a.x += v.x; a.y += v.y; a.z += v.z; a.w += v.w;
        }
        *(float4*)&g_ksum[i4] = a;
    }
}

// =============================================================================
// mid2: matrix = KX·Wv^T + ksum·bv^T ; vsum = Wv·xsum + N·bv
// =============================================================================
__global__ __launch_bounds__(256)
void mid2_kernel(const float* __restrict__ Wv, const float* __restrict__ bv)
{
    __shared__ float kxs[32 * 193];
    __shared__ float wvs[24 * 193];
    __shared__ float xsum_s[192];
    __shared__ float ksum_s[32];
    const int tid = threadIdx.x;
    const int b = blockIdx.x >> 3;
    const int c0 = (blockIdx.x & 7) * 24;

#pragma unroll
    for (int i = 0; i < 24; i++) {
        int idx = tid + 256 * i;
        int m = idx / 192, d = idx - m * 192;
        kxs[m * 193 + d] = g_kx[b * (CQ * C) + idx];
    }
#pragma unroll
    for (int i = 0; i < 18; i++) {
        int idx = tid + 256 * i;
        int r = idx / 192, d = idx - r * 192;
        wvs[r * 193 + d] = Wv[(size_t)(c0 + r) * C + d];
    }
    if (tid < 192) xsum_s[tid] = g_xsum[b * C + tid];
    if (tid < 32)  ksum_s[tid] = g_ksum[b * CQ + tid];
    __syncthreads();

#pragma unroll
    for (int e = 0; e < 3; e++) {
        int o = tid + 256 * e;
        int m = o / 24, c = o - m * 24;
        float acc = ksum_s[m] * bv[c0 + c];
#pragma unroll 8
        for (int d = 0; d < 192; d++)
            acc = fmaf(kxs[m * 193 + d], wvs[c * 193 + d], acc);
        g_mat[b * (CQ * C) + m * C + c0 + c] = acc;
    }
    if (tid < 24) {
        float acc = (float)NPIX * bv[c0 + tid];
#pragma unroll 8
        for (int d = 0; d < 192; d++)
            acc = fmaf(wvs[tid * 193 + d], xsum_s[d], acc);
        g_vsum[b * C + c0 + tid] = acc;
    }
}

// =============================================================================
// Pass 2: pure streaming GEMM.  out = gamma*ts*(vsum + Qn·matrix),
//         ts = 1/(N + Qn·(ksum+eps)); Qn read from g_qn. 2 barriers/subtile.
// =============================================================================
__global__ __launch_bounds__(256, 2)
void pass2_kernel(const float* __restrict__ gamma, float* __restrict__ out)
{
    __shared__ float mats[32 * 192];
    __shared__ float qns[32 * 64];
    __shared__ float ksum_s[32];
    __shared__ float vsum_s[192];

    const int tid  = threadIdx.x;
    const int b    = blockIdx.y;
    const int part = blockIdx.x;
    const int cg   = tid >> 4;          // ch-group (12 ch)
    const int qd   = 4 * (tid & 15);    // px quad
    const float gm = gamma[0];

#pragma unroll
    for (int i = 0; i < 24; i++)
        mats[tid + 256 * i] = g_mat[(size_t)b * CQ * C + tid + 256 * i];
    if (tid < 32)  ksum_s[tid] = g_ksum[b * CQ + tid] + 1e-6f;
    if (tid < 192) vsum_s[tid] = g_vsum[b * C + tid];

    const float* qnb = g_qn + (size_t)b * CQ * NPIX;
    float* outb = out + (size_t)b * C * NPIX;

    for (int s = 0; s < NSUBT; s++) {
        const int n0 = part * TILE + s * SUB;
        __syncthreads();   // A: qns reuse guard (also covers prologue on s=0)

        // ---- stage Qn tile [32][64] ----
#pragma unroll
        for (int i = 0; i < 2; i++) {
            int idx = tid + 256 * i;
            int m = idx >> 4, q = idx & 15;
            *(float4*)&qns[m * 64 + 4 * q] =
                *(const float4*)&qnb[(size_t)m * NPIX + n0 + 4 * q];
        }
        __syncthreads();   // B: qns ready

        // ---- ts for this thread's 4 px ----
        u64 sd0 = 0ull, sd1 = 0ull;
#pragma unroll 8
        for (int m = 0; m < CQ; m++) {
            ulonglong2 qv = *(const ulonglong2*)&qns[m * 64 + qd];
            u64 ks = pack2dup(ksum_s[m]);
            sd0 = ffma2(qv.x, ks, sd0);
            sd1 = ffma2(qv.y, ks, sd1);
        }
        float t0, t1, t2, t3;
        unpack2(sd0, t0, t1); unpack2(sd1, t2, t3);
        t0 = 1.0f / ((float)NPIX + t0); t1 = 1.0f / ((float)NPIX + t1);
        t2 = 1.0f / ((float)NPIX + t2); t3 = 1.0f / ((float)NPIX + t3);

        // ---- out GEMM: 4 px x 12 ch ----
        u64 oacc[4][6];
#pragma unroll
        for (int e = 0; e < 6; e++) {
            u64 vp = *(const u64*)&vsum_s[cg * 12 + 2 * e];
            oacc[0][e] = vp; oacc[1][e] = vp; oacc[2][e] = vp; oacc[3][e] = vp;
        }
#pragma unroll 4
        for (int m = 0; m < CQ; m++) {
            float4 qv = *(const float4*)&qns[m * 64 + qd];
            u64 q0 = pack2dup(qv.x), q1 = pack2dup(qv.y);
            u64 q2 = pack2dup(qv.z), q3 = pack2dup(qv.w);
#pragma unroll
            for (int j = 0; j < 3; j++) {
                ulonglong2 wv =
                    *(const ulonglong2*)&mats[m * 192 + cg * 12 + 4 * j];
                oacc[0][2*j]   = ffma2(wv.x, q0, oacc[0][2*j]);
                oacc[1][2*j]   = ffma2(wv.x, q1, oacc[1][2*j]);
                oacc[2][2*j]   = ffma2(wv.x, q2, oacc[2][2*j]);
                oacc[3][2*j]   = ffma2(wv.x, q3, oacc[3][2*j]);
                oacc[0][2*j+1] = ffma2(wv.y, q0, oacc[0][2*j+1]);
                oacc[1][2*j+1] = ffma2(wv.y, q1, oacc[1][2*j+1]);
                oacc[2][2*j+1] = ffma2(wv.y, q2, oacc[2][2*j+1]);
                oacc[3][2*j+1] = ffma2(wv.y, q3, oacc[3][2*j+1]);
            }
        }
        {
            u64 g0 = pack2dup(gm * t0), g1 = pack2dup(gm * t1);
            u64 g2 = pack2dup(gm * t2), g3 = pack2dup(gm * t3);
#pragma unroll
            for (int e = 0; e < 6; e++) {
                u64 o0 = fmul2(oacc[0][e], g0);
                u64 o1 = fmul2(oacc[1][e], g1);
                u64 o2 = fmul2(oacc[2][e], g2);
                u64 o3 = fmul2(oacc[3][e], g3);
                float l0, h0, l1, h1, l2, h2, l3, h3;
                unpack2(o0, l0, h0); unpack2(o1, l1, h1);
                unpack2(o2, l2, h2); unpack2(o3, l3, h3);
                const int c = cg * 12 + 2 * e;
                *(float4*)&outb[(size_t)c * NPIX + n0 + qd] =
                    make_float4(l0, l1, l2, l3);
                *(float4*)&outb[(size_t)(c + 1) * NPIX + n0 + qd] =
                    make_float4(h0, h1, h2, h3);
            }
        }
    }
}

// =============================================================================
extern "C" void kernel_launch(void* const* d_in, const int* in_sizes, int n_in,
                              void* d_out, int out_size)
{
    const float* x     = (const float*)d_in[0];
    const float* x1    = (const float*)d_in[1];
    const float* Wq    = (const float*)d_in[2];
    const float* bq    = (const float*)d_in[3];
    const float* Wk    = (const float*)d_in[4];
    const float* bk    = (const float*)d_in[5];
    const float* Wv    = (const float*)d_in[6];
    const float* bv    = (const float*)d_in[7];
    const float* gamma = (const float*)d_in[8];
    float* out = (float*)d_out;

    cudaFuncSetAttribute(pass1_kernel,
                         cudaFuncAttributeMaxDynamicSharedMemorySize, SMEM1_BYTES);

    dim3 grid(NPARTS, BATCH);
    pass1_kernel<<<grid, 256, SMEM1_BYTES>>>(x, x1, Wk, bk, Wq, bq);

    const int R4 = BATCH * CQ * C / 4 + BATCH * C / 4 + BATCH * CQ / 4;
    mid1_kernel<<<(R4 + 255) / 256, 256>>>();
    mid2_kernel<<<64, 256>>>(Wv, bv);

    pass2_kernel<<<grid, 256>>>(gamma, out);
}

// round 13
// speedup vs baseline: 1.4834x; 1.4834x over previous
#include <cuda_runtime.h>
#include <cstdint>

#define BATCH 8
#define C     192
#define CQ    32
#define NPIX  16384
#define SUB   64
#define NSUBT 4
#define TILE  (SUB*NSUBT)     // 256
#define NPARTS (NPIX/TILE)    // 64

typedef unsigned long long u64;

// ---------------- deterministic scratch ----------------
__device__ float g_part_kx  [BATCH*NPARTS*CQ*C];
__device__ float g_part_xsum[BATCH*NPARTS*C];
__device__ float g_part_ksum[BATCH*NPARTS*CQ];
__device__ float g_kx  [BATCH*CQ*C];
__device__ float g_xsum[BATCH*C];
__device__ float g_ksum[BATCH*CQ];
__device__ float g_mat [BATCH*CQ*C];
__device__ float g_vsum[BATCH*C];
__device__ float g_qn  [BATCH*CQ*NPIX];   // 16.8 MB: normalized Q

// ---------------- packed f32x2 helpers ----------------
__device__ __forceinline__ u64 pack2dup(float x) {
    u64 r; asm("mov.b64 %0, {%1, %1};" : "=l"(r) : "f"(x)); return r;
}
__device__ __forceinline__ u64 pack2(float a, float b) {
    u64 r; asm("mov.b64 %0, {%1, %2};" : "=l"(r) : "f"(a), "f"(b)); return r;
}
__device__ __forceinline__ void unpack2(u64 v, float& lo, float& hi) {
    asm("mov.b64 {%0, %1}, %2;" : "=f"(lo), "=f"(hi) : "l"(v));
}
__device__ __forceinline__ u64 ffma2(u64 a, u64 b, u64 c) {
    u64 d; asm("fma.rn.f32x2 %0, %1, %2, %3;" : "=l"(d) : "l"(a), "l"(b), "l"(c));
    return d;
}
__device__ __forceinline__ u64 fmul2(u64 a, u64 b) {
    u64 d; asm("mul.rn.f32x2 %0, %1, %2;" : "=l"(d) : "l"(a), "l"(b)); return d;
}
__device__ __forceinline__ u64 fadd2(u64 a, u64 b) {
    u64 d; asm("add.rn.f32x2 %0, %1, %2;" : "=l"(d) : "l"(a), "l"(b)); return d;
}

// ---------------- smem layout (pass1, float offsets) ----------------
#define P1_BUF0   0        // x1 [192][64] then xt [64][194] -> 12416
#define P1_WK     12416    // [32][196] = 6272
#define P1_WQ     18688    // [32][196] = 6272
#define P1_KN     24960    // [32][64]  = 2048
#define P1_KSQ    27008    // [8][64]   = 512
#define P1_QSQ    27520    // [8][64]   = 512
#define P1_INVN   28032    // [64]
#define P1_INVQ   28096    // [64]
#define P1_WKP    28160    // [32]
#define P1_KSUML  28192    // [32]
#define P1_TOT    28224
#define SMEM1_BYTES (P1_TOT*4)   // 112896 B; 2 CTAs/SM

// =============================================================================
// Pass 1: K-proj (lower half) + Q-proj (upper half) with x prefetch overlap;
//         Kn, KX = Kn·x^T, ksum, xsum; Qn -> g_qn
// =============================================================================
__global__ __launch_bounds__(256, 2)
void pass1_kernel(const float* __restrict__ x, const float* __restrict__ x1,
                  const float* __restrict__ Wk, const float* __restrict__ bk,
                  const float* __restrict__ Wq, const float* __restrict__ bq)
{
    extern __shared__ float sm[];
    float* buf0  = sm + P1_BUF0;
    float* wk    = sm + P1_WK;
    float* wq    = sm + P1_WQ;
    float* kn    = sm + P1_KN;
    float* ksq   = sm + P1_KSQ;
    float* qsq   = sm + P1_QSQ;
    float* invn  = sm + P1_INVN;
    float* invq  = sm + P1_INVQ;
    float* wkp   = sm + P1_WKP;
    float* ksuml = sm + P1_KSUML;

    const int tid  = threadIdx.x;
    const int lane = tid & 31;
    const int wgrp = tid >> 5;
    const int b    = blockIdx.y;
    const int part = blockIdx.x;
    const int pl   = 2 * lane;
    const int ph   = tid >> 7;          // 0 = K half, 1 = Q half
    const int u    = tid & 127;
    const int mg   = u >> 4;            // m-group (4 m)
    const int qd   = 4 * (u & 15);      // px quad

    // stage both weight matrices, stride 196 (16B-aligned rows)
#pragma unroll
    for (int i = 0; i < 24; i++) {
        int idx = tid + 256 * i;
        int m = idx / 192, k = idx - m * 192;
        wk[m * 196 + k] = Wk[idx];
        wq[m * 196 + k] = Wq[idx];
    }
    if (tid < 32) ksuml[tid] = 0.f;

    float br[4];
#pragma unroll
    for (int mi = 0; mi < 4; mi++)
        br[mi] = ph ? bq[mg * 4 + mi] : bk[mg * 4 + mi];
    const float* wsel = ph ? wq : wk;
    float* sqdst = ph ? qsq : ksq;

    u64 macc[4][3];
#pragma unroll
    for (int i = 0; i < 4; i++)
#pragma unroll
        for (int j = 0; j < 3; j++) macc[i][j] = 0ull;
    u64 xacc = 0ull;

    const float* x1b = x1 + (size_t)b * C * NPIX;
    const float* xb  = x  + (size_t)b * C * NPIX;
    float* qnb = g_qn + (size_t)b * CQ * NPIX;

    for (int s = 0; s < NSUBT; s++) {
        const int n0 = part * TILE + s * SUB;
        __syncthreads();   // A: buf0/kn reuse guard

        // ---- stage x1 -> buf0[c][t] stride 64 (all threads) ----
#pragma unroll
        for (int i = 0; i < 12; i++) {
            int idx = tid + 256 * i;
            int c = idx >> 4, q = idx & 15;
            *(float4*)&buf0[c * 64 + 4 * q] =
                *(const float4*)&x1b[(size_t)c * NPIX + n0 + 4 * q];
        }
        __syncthreads();   // B

        // ---- PREFETCH x first half (channels 0..95) — overlaps the proj ----
        float4 xr[6];
#pragma unroll
        for (int i = 0; i < 6; i++) {
            int idx = tid + 256 * i;
            int c = idx >> 4, q = idx & 15;
            xr[i] = *(const float4*)&xb[(size_t)c * NPIX + n0 + 4 * q];
        }

        // ---- projection (K on lower half, Q on upper half) ----
        u64 acc[4][2];
#pragma unroll
        for (int mi = 0; mi < 4; mi++) {
            u64 bb = pack2dup(br[mi]);
            acc[mi][0] = bb; acc[mi][1] = bb;
        }
#pragma unroll 3
        for (int k = 0; k < C; k += 4) {
            ulonglong2 xA = *(const ulonglong2*)&buf0[k * 64 + qd];
            ulonglong2 xC = *(const ulonglong2*)&buf0[(k + 1) * 64 + qd];
            ulonglong2 xE = *(const ulonglong2*)&buf0[(k + 2) * 64 + qd];
            ulonglong2 xG = *(const ulonglong2*)&buf0[(k + 3) * 64 + qd];
#pragma unroll
            for (int mi = 0; mi < 4; mi++) {
                float4 w = *(const float4*)&wsel[(mg * 4 + mi) * 196 + k];
                u64 w0 = pack2dup(w.x), w1 = pack2dup(w.y);
                u64 w2 = pack2dup(w.z), w3 = pack2dup(w.w);
                acc[mi][0] = ffma2(xA.x, w0, acc[mi][0]);
                acc[mi][1] = ffma2(xA.y, w0, acc[mi][1]);
                acc[mi][0] = ffma2(xC.x, w1, acc[mi][0]);
                acc[mi][1] = ffma2(xC.y, w1, acc[mi][1]);
                acc[mi][0] = ffma2(xE.x, w2, acc[mi][0]);
                acc[mi][1] = ffma2(xE.y, w2, acc[mi][1]);
                acc[mi][0] = ffma2(xG.x, w3, acc[mi][0]);
                acc[mi][1] = ffma2(xG.y, w3, acc[mi][1]);
            }
        }
        {
            u64 sq0 = fmul2(acc[0][0], acc[0][0]);
            u64 sq1 = fmul2(acc[0][1], acc[0][1]);
#pragma unroll
            for (int mi = 1; mi < 4; mi++) {
                sq0 = ffma2(acc[mi][0], acc[mi][0], sq0);
                sq1 = ffma2(acc[mi][1], acc[mi][1], sq1);
            }
            *(u64*)&sqdst[mg * 64 + qd]     = sq0;
            *(u64*)&sqdst[mg * 64 + qd + 2] = sq1;
        }
        __syncthreads();   // C: proj reads done, ksq+qsq ready

        if (tid < 64) {
            float tot = 0.f;
#pragma unroll
            for (int g = 0; g < 8; g++) tot += ksq[g * 64 + tid];
            invn[tid] = rsqrtf(tot);
        } else if (tid < 128) {
            const int t = tid - 64;
            float tot = 0.f;
#pragma unroll
            for (int g = 0; g < 8; g++) tot += qsq[g * 64 + t];
            invq[t] = rsqrtf(tot);
        }
        // ---- issue second-half x loads (in flight during xr stores) ----
        float4 xr2[6];
#pragma unroll
        for (int i = 0; i < 6; i++) {
            int idx = tid + 256 * (i + 6);
            int c = idx >> 4, q = idx & 15;
            xr2[i] = *(const float4*)&xb[(size_t)c * NPIX + n0 + 4 * q];
        }
        // ---- store prefetched first half transposed -> xt[t][194] ----
#pragma unroll
        for (int i = 0; i < 6; i++) {
            int idx = tid + 256 * i;
            int c = idx >> 4, q = idx & 15;
            buf0[(4 * q)     * 194 + c] = xr[i].x;
            buf0[(4 * q + 1) * 194 + c] = xr[i].y;
            buf0[(4 * q + 2) * 194 + c] = xr[i].z;
            buf0[(4 * q + 3) * 194 + c] = xr[i].w;
        }
        // ---- store second half ----
#pragma unroll
        for (int i = 0; i < 6; i++) {
            int idx = tid + 256 * (i + 6);
            int c = idx >> 4, q = idx & 15;
            buf0[(4 * q)     * 194 + c] = xr2[i].x;
            buf0[(4 * q + 1) * 194 + c] = xr2[i].y;
            buf0[(4 * q + 2) * 194 + c] = xr2[i].z;
            buf0[(4 * q + 3) * 194 + c] = xr2[i].w;
        }
        __syncthreads();   // D: invn/invq + xt ready

        if (ph == 0) {
            // ---- kn = K*inv (float4 store), ksum via 16-lane shfl ----
            float4 iv = *(const float4*)&invn[qd];
            u64 iv0 = pack2(iv.x, iv.y), iv1 = pack2(iv.z, iv.w);
            float ksump[4];
#pragma unroll
            for (int mi = 0; mi < 4; mi++) {
                u64 k0 = fmul2(acc[mi][0], iv0);
                u64 k1 = fmul2(acc[mi][1], iv1);
                float a0, a1, a2, a3;
                unpack2(k0, a0, a1); unpack2(k1, a2, a3);
                *(float4*)&kn[(mg * 4 + mi) * 64 + qd] =
                    make_float4(a0, a1, a2, a3);
                ksump[mi] = (a0 + a1) + (a2 + a3);
            }
#pragma unroll
            for (int off = 8; off; off >>= 1)
#pragma unroll
                for (int mi = 0; mi < 4; mi++)
                    ksump[mi] += __shfl_down_sync(0xffffffffu, ksump[mi], off, 16);
            if ((u & 15) == 0)
#pragma unroll
                for (int mi = 0; mi < 4; mi++) wkp[mg * 4 + mi] = ksump[mi];
        } else {
            // ---- qn = Q*invq -> g_qn (STG.128 per m) ----
            float4 iv = *(const float4*)&invq[qd];
            u64 iv0 = pack2(iv.x, iv.y), iv1 = pack2(iv.z, iv.w);
#pragma unroll
            for (int mi = 0; mi < 4; mi++) {
                u64 q0 = fmul2(acc[mi][0], iv0);
                u64 q1 = fmul2(acc[mi][1], iv1);
                float a0, a1, a2, a3;
                unpack2(q0, a0, a1); unpack2(q1, a2, a3);
                *(float4*)&qnb[(size_t)(mg * 4 + mi) * NPIX + n0 + qd] =
                    make_float4(a0, a1, a2, a3);
            }
        }
        __syncthreads();   // E: kn + wkp ready

        if (tid < 32) ksuml[tid] += wkp[tid];

        // ---- xsum partial ----
        if (tid < 96) {
            u64 sv = 0ull;
#pragma unroll 8
            for (int t = 0; t < SUB; t++)
                sv = fadd2(sv, *(const u64*)&buf0[t * 194 + 2 * tid]);
            xacc = fadd2(xacc, sv);
        }

        // ---- KX += kn·x^T (t-block-4, broadcast kn LDS.128) ----
#pragma unroll 4
        for (int tb = 0; tb < 16; tb++) {
            const int t0 = 4 * tb;
            float4 kd[4];
#pragma unroll
            for (int i = 0; i < 4; i++)
                kd[i] = *(const float4*)&kn[(wgrp + 8 * i) * 64 + t0];
#pragma unroll
            for (int tt = 0; tt < 4; tt++) {
                u64 x2[3];
#pragma unroll
                for (int j = 0; j < 3; j++)
                    x2[j] = *(const u64*)&buf0[(t0 + tt) * 194 + pl + 64 * j];
                const float* kf0 = (const float*)&kd[0];
                const float* kf1 = (const float*)&kd[1];
                const float* kf2 = (const float*)&kd[2];
                const float* kf3 = (const float*)&kd[3];
                u64 kd0 = pack2dup(kf0[tt]);
                u64 kd1 = pack2dup(kf1[tt]);
                u64 kd2 = pack2dup(kf2[tt]);
                u64 kd3 = pack2dup(kf3[tt]);
#pragma unroll
                for (int j = 0; j < 3; j++) {
                    macc[0][j] = ffma2(kd0, x2[j], macc[0][j]);
                    macc[1][j] = ffma2(kd1, x2[j], macc[1][j]);
                    macc[2][j] = ffma2(kd2, x2[j], macc[2][j]);
                    macc[3][j] = ffma2(kd3, x2[j], macc[3][j]);
                }
            }
        }
    }

    __syncthreads();
    float* pm = g_part_kx + ((size_t)b * NPARTS + part) * CQ * C;
#pragma unroll
    for (int i = 0; i < 4; i++)
#pragma unroll
        for (int j = 0; j < 3; j++)
            *(u64*)&pm[(wgrp + 8 * i) * C + pl + 64 * j] = macc[i][j];
    if (tid < 96) {
        float lo, hi; unpack2(xacc, lo, hi);
        float* px = g_part_xsum + ((size_t)b * NPARTS + part) * C;
        px[2 * tid] = lo; px[2 * tid + 1] = hi;
    }
    if (tid < 32) g_part_ksum[((size_t)b * NPARTS + part) * CQ + tid] = ksuml[tid];
}

// =============================================================================
// mid1: reduce partials (fixed order, float4)
// =============================================================================
__global__ void mid1_kernel()
{
    const int MAT4 = BATCH * CQ * C / 4;
    const int XS4  = BATCH * C / 4;
    const int KS4  = BATCH * CQ / 4;
    int idx = blockIdx.x * blockDim.x + threadIdx.x;
    if (idx < MAT4) {
        int i4 = idx * 4;
        int bb = i4 / (CQ * C), r = i4 % (CQ * C);
        const float* p = g_part_kx + (size_t)bb * NPARTS * CQ * C + r;
        float4 a = make_float4(0.f, 0.f, 0.f, 0.f);
#pragma unroll 8
        for (int q = 0; q < NPARTS; q++) {
            float4 v = *(const float4*)&p[(size_t)q * CQ * C];
            a.x += v.x; a.y += v.y; a.z += v.z; a.w += v.w;
        }
        *(float4*)&g_kx[i4] = a;
    } else if (idx < MAT4 + XS4) {
        int i4 = (idx - MAT4) * 4;
        int bb = i4 / C, r = i4 % C;
        const float* p = g_part_xsum + (size_t)bb * NPARTS * C + r;
        float4 a = make_float4(0.f, 0.f, 0.f, 0.f);
#pragma unroll 8
        for (int q = 0; q < NPARTS; q++) {
            float4 v = *(const float4*)&p[q * C];
            a.x += v.x; a.y += v.y; a.z += v.z; a.w += v.w;
        }
        *(float4*)&g_xsum[i4] = a;
    } else if (idx < MAT4 + XS4 + KS4) {
        int i4 = (idx - MAT4 - XS4) * 4;
        int bb = i4 / CQ, r = i4 % CQ;
        const float* p = g_part_ksum + (size_t)bb * NPARTS * CQ + r;
        float4 a = make_float4(0.f, 0.f, 0.f, 0.f);
#pragma unroll 8
        for (int q = 0; q < NPARTS; q++) {
            float4 v = *(const float4*)&p[q * CQ];
            a.x += v.x; a.y += v.y; a.z += v.z; a.w += v.w;
        }
        *(float4*)&g_ksum[i4] = a;
    }
}

// =============================================================================
// mid2: matrix = KX·Wv^T + ksum·bv^T ; vsum = Wv·xsum + N·bv
// =============================================================================
__global__ __launch_bounds__(256)
void mid2_kernel(const float* __restrict__ Wv, const float* __restrict__ bv)
{
    __shared__ float kxs[32 * 193];
    __shared__ float wvs[24 * 193];
    __shared__ float xsum_s[192];
    __shared__ float ksum_s[32];
    const int tid = threadIdx.x;
    const int b = blockIdx.x >> 3;
    const int c0 = (blockIdx.x & 7) * 24;

#pragma unroll
    for (int i = 0; i < 24; i++) {
        int idx = tid + 256 * i;
        int m = idx / 192, d = idx - m * 192;
        kxs[m * 193 + d] = g_kx[b * (CQ * C) + idx];
    }
#pragma unroll
    for (int i = 0; i < 18; i++) {
        int idx = tid + 256 * i;
        int r = idx / 192, d = idx - r * 192;
        wvs[r * 193 + d] = Wv[(size_t)(c0 + r) * C + d];
    }
    if (tid < 192) xsum_s[tid] = g_xsum[b * C + tid];
    if (tid < 32)  ksum_s[tid] = g_ksum[b * CQ + tid];
    __syncthreads();

#pragma unroll
    for (int e = 0; e < 3; e++) {
        int o = tid + 256 * e;
        int m = o / 24, c = o - m * 24;
        float acc = ksum_s[m] * bv[c0 + c];
#pragma unroll 8
        for (int d = 0; d < 192; d++)
            acc = fmaf(kxs[m * 193 + d], wvs[c * 193 + d], acc);
        g_mat[b * (CQ * C) + m * C + c0 + c] = acc;
    }
    if (tid < 24) {
        float acc = (float)NPIX * bv[c0 + tid];
#pragma unroll 8
        for (int d = 0; d < 192; d++)
            acc = fmaf(wvs[tid * 193 + d], xsum_s[d], acc);
        g_vsum[b * C + c0 + tid] = acc;
    }
}

// =============================================================================
// Pass 2: pure streaming GEMM (measured 91 us) — unchanged from R12
// =============================================================================
__global__ __launch_bounds__(256, 2)
void pass2_kernel(const float* __restrict__ gamma, float* __restrict__ out)
{
    __shared__ float mats[32 * 192];
    __shared__ float qns[32 * 64];
    __shared__ float ksum_s[32];
    __shared__ float vsum_s[192];

    const int tid  = threadIdx.x;
    const int b    = blockIdx.y;
    const int part = blockIdx.x;
    const int cg   = tid >> 4;
    const int qd   = 4 * (tid & 15);
    const float gm = gamma[0];

#pragma unroll
    for (int i = 0; i < 24; i++)
        mats[tid + 256 * i] = g_mat[(size_t)b * CQ * C + tid + 256 * i];
    if (tid < 32)  ksum_s[tid] = g_ksum[b * CQ + tid] + 1e-6f;
    if (tid < 192) vsum_s[tid] = g_vsum[b * C + tid];

    const float* qnb = g_qn + (size_t)b * CQ * NPIX;
    float* outb = out + (size_t)b * C * NPIX;

    for (int s = 0; s < NSUBT; s++) {
        const int n0 = part * TILE + s * SUB;
        __syncthreads();   // A

#pragma unroll
        for (int i = 0; i < 2; i++) {
            int idx = tid + 256 * i;
            int m = idx >> 4, q = idx & 15;
            *(float4*)&qns[m * 64 + 4 * q] =
                *(const float4*)&qnb[(size_t)m * NPIX + n0 + 4 * q];
        }
        __syncthreads();   // B

        u64 sd0 = 0ull, sd1 = 0ull;
#pragma unroll 8
        for (int m = 0; m < CQ; m++) {
            ulonglong2 qv = *(const ulonglong2*)&qns[m * 64 + qd];
            u64 ks = pack2dup(ksum_s[m]);
            sd0 = ffma2(qv.x, ks, sd0);
            sd1 = ffma2(qv.y, ks, sd1);
        }
        float t0, t1, t2, t3;
        unpack2(sd0, t0, t1); unpack2(sd1, t2, t3);
        t0 = 1.0f / ((float)NPIX + t0); t1 = 1.0f / ((float)NPIX + t1);
        t2 = 1.0f / ((float)NPIX + t2); t3 = 1.0f / ((float)NPIX + t3);

        u64 oacc[4][6];
#pragma unroll
        for (int e = 0; e < 6; e++) {
            u64 vp = *(const u64*)&vsum_s[cg * 12 + 2 * e];
            oacc[0][e] = vp; oacc[1][e] = vp; oacc[2][e] = vp; oacc[3][e] = vp;
        }
#pragma unroll 4
        for (int m = 0; m < CQ; m++) {
            float4 qv = *(const float4*)&qns[m * 64 + qd];
            u64 q0 = pack2dup(qv.x), q1 = pack2dup(qv.y);
            u64 q2 = pack2dup(qv.z), q3 = pack2dup(qv.w);
#pragma unroll
            for (int j = 0; j < 3; j++) {
                ulonglong2 wv =
                    *(const ulonglong2*)&mats[m * 192 + cg * 12 + 4 * j];
                oacc[0][2*j]   = ffma2(wv.x, q0, oacc[0][2*j]);
                oacc[1][2*j]   = ffma2(wv.x, q1, oacc[1][2*j]);
                oacc[2][2*j]   = ffma2(wv.x, q2, oacc[2][2*j]);
                oacc[3][2*j]   = ffma2(wv.x, q3, oacc[3][2*j]);
                oacc[0][2*j+1] = ffma2(wv.y, q0, oacc[0][2*j+1]);
                oacc[1][2*j+1] = ffma2(wv.y, q1, oacc[1][2*j+1]);
                oacc[2][2*j+1] = ffma2(wv.y, q2, oacc[2][2*j+1]);
                oacc[3][2*j+1] = ffma2(wv.y, q3, oacc[3][2*j+1]);
            }
        }
        {
            u64 g0 = pack2dup(gm * t0), g1 = pack2dup(gm * t1);
            u64 g2 = pack2dup(gm * t2), g3 = pack2dup(gm * t3);
#pragma unroll
            for (int e = 0; e < 6; e++) {
                u64 o0 = fmul2(oacc[0][e], g0);
                u64 o1 = fmul2(oacc[1][e], g1);
                u64 o2 = fmul2(oacc[2][e], g2);
                u64 o3 = fmul2(oacc[3][e], g3);
                float l0, h0, l1, h1, l2, h2, l3, h3;
                unpack2(o0, l0, h0); unpack2(o1, l1, h1);
                unpack2(o2, l2, h2); unpack2(o3, l3, h3);
                const int c = cg * 12 + 2 * e;
                *(float4*)&outb[(size_t)c * NPIX + n0 + qd] =
                    make_float4(l0, l1, l2, l3);
                *(float4*)&outb[(size_t)(c + 1) * NPIX + n0 + qd] =
                    make_float4(h0, h1, h2, h3);
            }
        }
    }
}

// =============================================================================
extern "C" void kernel_launch(void* const* d_in, const int* in_sizes, int n_in,
                              void* d_out, int out_size)
{
    const float* x     = (const float*)d_in[0];
    const float* x1    = (const float*)d_in[1];
    const float* Wq    = (const float*)d_in[2];
    const float* bq    = (const float*)d_in[3];
    const float* Wk    = (const float*)d_in[4];
    const float* bk    = (const float*)d_in[5];
    const float* Wv    = (const float*)d_in[6];
    const float* bv    = (const float*)d_in[7];
    const float* gamma = (const float*)d_in[8];
    float* out = (float*)d_out;

    cudaFuncSetAttribute(pass1_kernel,
                         cudaFuncAttributeMaxDynamicSharedMemorySize, SMEM1_BYTES);

    dim3 grid(NPARTS, BATCH);
    pass1_kernel<<<grid, 256, SMEM1_BYTES>>>(x, x1, Wk, bk, Wq, bq);

    const int R4 = BATCH * CQ * C / 4 + BATCH * C / 4 + BATCH * CQ / 4;
    mid1_kernel<<<(R4 + 255) / 256, 256>>>();
    mid2_kernel<<<64, 256>>>(Wv, bv);

    pass2_kernel<<<grid, 256>>>(gamma, out);
}

// round 14
// speedup vs baseline: 1.5748x; 1.0617x over previous
#include <cuda_runtime.h>
#include <cstdint>

#define BATCH 8
#define C     192
#define CQ    32
#define NPIX  16384
#define SUB   64
#define NSUBT 2
#define TILE  (SUB*NSUBT)     // 128
#define NPARTS (NPIX/TILE)    // 128

typedef unsigned long long u64;

// ---------------- deterministic scratch ----------------
__device__ float g_part_kx  [BATCH*NPARTS*CQ*C];   // 25.2 MB
__device__ float g_part_xsum[BATCH*NPARTS*C];
__device__ float g_part_ksum[BATCH*NPARTS*CQ];
__device__ float g_kx  [BATCH*CQ*C];
__device__ float g_xsum[BATCH*C];
__device__ float g_ksum[BATCH*CQ];
__device__ float g_mat [BATCH*CQ*C];
__device__ float g_vsum[BATCH*C];
__device__ float g_qn  [BATCH*CQ*NPIX];   // 16.8 MB: normalized Q

// ---------------- packed f32x2 helpers ----------------
__device__ __forceinline__ u64 pack2dup(float x) {
    u64 r; asm("mov.b64 %0, {%1, %1};" : "=l"(r) : "f"(x)); return r;
}
__device__ __forceinline__ u64 pack2(float a, float b) {
    u64 r; asm("mov.b64 %0, {%1, %2};" : "=l"(r) : "f"(a), "f"(b)); return r;
}
__device__ __forceinline__ void unpack2(u64 v, float& lo, float& hi) {
    asm("mov.b64 {%0, %1}, %2;" : "=f"(lo), "=f"(hi) : "l"(v));
}
__device__ __forceinline__ u64 ffma2(u64 a, u64 b, u64 c) {
    u64 d; asm("fma.rn.f32x2 %0, %1, %2, %3;" : "=l"(d) : "l"(a), "l"(b), "l"(c));
    return d;
}
__device__ __forceinline__ u64 fmul2(u64 a, u64 b) {
    u64 d; asm("mul.rn.f32x2 %0, %1, %2;" : "=l"(d) : "l"(a), "l"(b)); return d;
}
__device__ __forceinline__ u64 fadd2(u64 a, u64 b) {
    u64 d; asm("add.rn.f32x2 %0, %1, %2;" : "=l"(d) : "l"(a), "l"(b)); return d;
}

// ---------------- smem layout (pass1, float offsets) ----------------
#define P1_BUF0   0        // x1 [192][64] then xt [64][194] -> 12416
#define P1_WK     12416    // [32][196] = 6272
#define P1_WQ     18688    // [32][196] = 6272
#define P1_KN     24960    // [32][64]  = 2048
#define P1_KSQ    27008    // [8][64]   = 512
#define P1_QSQ    27520    // [8][64]   = 512
#define P1_INVN   28032    // [64]
#define P1_INVQ   28096    // [64]
#define P1_WKP    28160    // [32]
#define P1_KSUML  28192    // [32]
#define P1_TOT    28224
#define SMEM1_BYTES (P1_TOT*4)   // 112896 B; 2 CTAs/SM

// =============================================================================
// Pass 1: K-proj (lower half) + Q-proj (upper half) with x prefetch overlap;
//         Kn, KX = Kn·x^T, ksum, xsum; Qn -> g_qn
// =============================================================================
__global__ __launch_bounds__(256, 2)
void pass1_kernel(const float* __restrict__ x, const float* __restrict__ x1,
                  const float* __restrict__ Wk, const float* __restrict__ bk,
                  const float* __restrict__ Wq, const float* __restrict__ bq)
{
    extern __shared__ float sm[];
    float* buf0  = sm + P1_BUF0;
    float* wk    = sm + P1_WK;
    float* wq    = sm + P1_WQ;
    float* kn    = sm + P1_KN;
    float* ksq   = sm + P1_KSQ;
    float* qsq   = sm + P1_QSQ;
    float* invn  = sm + P1_INVN;
    float* invq  = sm + P1_INVQ;
    float* wkp   = sm + P1_WKP;
    float* ksuml = sm + P1_KSUML;

    const int tid  = threadIdx.x;
    const int lane = tid & 31;
    const int wgrp = tid >> 5;
    const int b    = blockIdx.y;
    const int part = blockIdx.x;
    const int pl   = 2 * lane;
    const int ph   = tid >> 7;          // 0 = K half, 1 = Q half
    const int u    = tid & 127;
    const int mg   = u >> 4;            // m-group (4 m)
    const int qd   = 4 * (u & 15);      // px quad

    // stage both weight matrices, stride 196 (16B-aligned rows)
#pragma unroll
    for (int i = 0; i < 24; i++) {
        int idx = tid + 256 * i;
        int m = idx / 192, k = idx - m * 192;
        wk[m * 196 + k] = Wk[idx];
        wq[m * 196 + k] = Wq[idx];
    }
    if (tid < 32) ksuml[tid] = 0.f;

    float br[4];
#pragma unroll
    for (int mi = 0; mi < 4; mi++)
        br[mi] = ph ? bq[mg * 4 + mi] : bk[mg * 4 + mi];
    const float* wsel = ph ? wq : wk;
    float* sqdst = ph ? qsq : ksq;

    u64 macc[4][3];
#pragma unroll
    for (int i = 0; i < 4; i++)
#pragma unroll
        for (int j = 0; j < 3; j++) macc[i][j] = 0ull;
    u64 xacc = 0ull;

    const float* x1b = x1 + (size_t)b * C * NPIX;
    const float* xb  = x  + (size_t)b * C * NPIX;
    float* qnb = g_qn + (size_t)b * CQ * NPIX;

    for (int s = 0; s < NSUBT; s++) {
        const int n0 = part * TILE + s * SUB;
        __syncthreads();   // A: buf0/kn reuse guard

        // ---- stage x1 -> buf0[c][t] stride 64 (all threads) ----
#pragma unroll
        for (int i = 0; i < 12; i++) {
            int idx = tid + 256 * i;
            int c = idx >> 4, q = idx & 15;
            *(float4*)&buf0[c * 64 + 4 * q] =
                *(const float4*)&x1b[(size_t)c * NPIX + n0 + 4 * q];
        }
        __syncthreads();   // B

        // ---- PREFETCH x first half (channels 0..95) — overlaps the proj ----
        float4 xr[6];
#pragma unroll
        for (int i = 0; i < 6; i++) {
            int idx = tid + 256 * i;
            int c = idx >> 4, q = idx & 15;
            xr[i] = *(const float4*)&xb[(size_t)c * NPIX + n0 + 4 * q];
        }

        // ---- projection (K on lower half, Q on upper half) ----
        u64 acc[4][2];
#pragma unroll
        for (int mi = 0; mi < 4; mi++) {
            u64 bb = pack2dup(br[mi]);
            acc[mi][0] = bb; acc[mi][1] = bb;
        }
#pragma unroll 3
        for (int k = 0; k < C; k += 4) {
            ulonglong2 xA = *(const ulonglong2*)&buf0[k * 64 + qd];
            ulonglong2 xC = *(const ulonglong2*)&buf0[(k + 1) * 64 + qd];
            ulonglong2 xE = *(const ulonglong2*)&buf0[(k + 2) * 64 + qd];
            ulonglong2 xG = *(const ulonglong2*)&buf0[(k + 3) * 64 + qd];
#pragma unroll
            for (int mi = 0; mi < 4; mi++) {
                float4 w = *(const float4*)&wsel[(mg * 4 + mi) * 196 + k];
                u64 w0 = pack2dup(w.x), w1 = pack2dup(w.y);
                u64 w2 = pack2dup(w.z), w3 = pack2dup(w.w);
                acc[mi][0] = ffma2(xA.x, w0, acc[mi][0]);
                acc[mi][1] = ffma2(xA.y, w0, acc[mi][1]);
                acc[mi][0] = ffma2(xC.x, w1, acc[mi][0]);
                acc[mi][1] = ffma2(xC.y, w1, acc[mi][1]);
                acc[mi][0] = ffma2(xE.x, w2, acc[mi][0]);
                acc[mi][1] = ffma2(xE.y, w2, acc[mi][1]);
                acc[mi][0] = ffma2(xG.x, w3, acc[mi][0]);
                acc[mi][1] = ffma2(xG.y, w3, acc[mi][1]);
            }
        }
        {
            u64 sq0 = fmul2(acc[0][0], acc[0][0]);
            u64 sq1 = fmul2(acc[0][1], acc[0][1]);
#pragma unroll
            for (int mi = 1; mi < 4; mi++) {
                sq0 = ffma2(acc[mi][0], acc[mi][0], sq0);
                sq1 = ffma2(acc[mi][1], acc[mi][1], sq1);
            }
            *(u64*)&sqdst[mg * 64 + qd]     = sq0;
            *(u64*)&sqdst[mg * 64 + qd + 2] = sq1;
        }
        __syncthreads();   // C: proj reads done, ksq+qsq ready

        if (tid < 64) {
            float tot = 0.f;
#pragma unroll
            for (int g = 0; g < 8; g++) tot += ksq[g * 64 + tid];
            invn[tid] = rsqrtf(tot);
        } else if (tid < 128) {
            const int t = tid - 64;
            float tot = 0.f;
#pragma unroll
            for (int g = 0; g < 8; g++) tot += qsq[g * 64 + t];
            invq[t] = rsqrtf(tot);
        }
        // ---- issue second-half x loads (in flight during xr stores) ----
        float4 xr2[6];
#pragma unroll
        for (int i = 0; i < 6; i++) {
            int idx = tid + 256 * (i + 6);
            int c = idx >> 4, q = idx & 15;
            xr2[i] = *(const float4*)&xb[(size_t)c * NPIX + n0 + 4 * q];
        }
        // ---- store prefetched first half transposed -> xt[t][194] ----
#pragma unroll
        for (int i = 0; i < 6; i++) {
            int idx = tid + 256 * i;
            int c = idx >> 4, q = idx & 15;
            buf0[(4 * q)     * 194 + c] = xr[i].x;
            buf0[(4 * q + 1) * 194 + c] = xr[i].y;
            buf0[(4 * q + 2) * 194 + c] = xr[i].z;
            buf0[(4 * q + 3) * 194 + c] = xr[i].w;
        }
        // ---- store second half ----
#pragma unroll
        for (int i = 0; i < 6; i++) {
            int idx = tid + 256 * (i + 6);
            int c = idx >> 4, q = idx & 15;
            buf0[(4 * q)     * 194 + c] = xr2[i].x;
            buf0[(4 * q + 1) * 194 + c] = xr2[i].y;
            buf0[(4 * q + 2) * 194 + c] = xr2[i].z;
            buf0[(4 * q + 3) * 194 + c] = xr2[i].w;
        }
        __syncthreads();   // D: invn/invq + xt ready

        if (ph == 0) {
            // ---- kn = K*inv (float4 store), ksum via 16-lane shfl ----
            float4 iv = *(const float4*)&invn[qd];
            u64 iv0 = pack2(iv.x, iv.y), iv1 = pack2(iv.z, iv.w);
            float ksump[4];
#pragma unroll
            for (int mi = 0; mi < 4; mi++) {
                u64 k0 = fmul2(acc[mi][0], iv0);
                u64 k1 = fmul2(acc[mi][1], iv1);
                float a0, a1, a2, a3;
                unpack2(k0, a0, a1); unpack2(k1, a2, a3);
                *(float4*)&kn[(mg * 4 + mi) * 64 + qd] =
                    make_float4(a0, a1, a2, a3);
                ksump[mi] = (a0 + a1) + (a2 + a3);
            }
#pragma unroll
            for (int off = 8; off; off >>= 1)
#pragma unroll
                for (int mi = 0; mi < 4; mi++)
                    ksump[mi] += __shfl_down_sync(0xffffffffu, ksump[mi], off, 16);
            if ((u & 15) == 0)
#pragma unroll
                for (int mi = 0; mi < 4; mi++) wkp[mg * 4 + mi] = ksump[mi];
        } else {
            // ---- qn = Q*invq -> g_qn (STG.128 per m) ----
            float4 iv = *(const float4*)&invq[qd];
            u64 iv0 = pack2(iv.x, iv.y), iv1 = pack2(iv.z, iv.w);
#pragma unroll
            for (int mi = 0; mi < 4; mi++) {
                u64 q0 = fmul2(acc[mi][0], iv0);
                u64 q1 = fmul2(acc[mi][1], iv1);
                float a0, a1, a2, a3;
                unpack2(q0, a0, a1); unpack2(q1, a2, a3);
                *(float4*)&qnb[(size_t)(mg * 4 + mi) * NPIX + n0 + qd] =
                    make_float4(a0, a1, a2, a3);
            }
        }
        __syncthreads();   // E: kn + wkp ready

        if (tid < 32) ksuml[tid] += wkp[tid];

        // ---- xsum partial ----
        if (tid < 96) {
            u64 sv = 0ull;
#pragma unroll 8
            for (int t = 0; t < SUB; t++)
                sv = fadd2(sv, *(const u64*)&buf0[t * 194 + 2 * tid]);
            xacc = fadd2(xacc, sv);
        }

        // ---- KX += kn·x^T (t-block-4, broadcast kn LDS.128) ----
#pragma unroll 4
        for (int tb = 0; tb < 16; tb++) {
            const int t0 = 4 * tb;
            float4 kd[4];
#pragma unroll
            for (int i = 0; i < 4; i++)
                kd[i] = *(const float4*)&kn[(wgrp + 8 * i) * 64 + t0];
#pragma unroll
            for (int tt = 0; tt < 4; tt++) {
                u64 x2[3];
#pragma unroll
                for (int j = 0; j < 3; j++)
                    x2[j] = *(const u64*)&buf0[(t0 + tt) * 194 + pl + 64 * j];
                const float* kf0 = (const float*)&kd[0];
                const float* kf1 = (const float*)&kd[1];
                const float* kf2 = (const float*)&kd[2];
                const float* kf3 = (const float*)&kd[3];
                u64 kd0 = pack2dup(kf0[tt]);
                u64 kd1 = pack2dup(kf1[tt]);
                u64 kd2 = pack2dup(kf2[tt]);
                u64 kd3 = pack2dup(kf3[tt]);
#pragma unroll
                for (int j = 0; j < 3; j++) {
                    macc[0][j] = ffma2(kd0, x2[j], macc[0][j]);
                    macc[1][j] = ffma2(kd1, x2[j], macc[1][j]);
                    macc[2][j] = ffma2(kd2, x2[j], macc[2][j]);
                    macc[3][j] = ffma2(kd3, x2[j], macc[3][j]);
                }
            }
        }
    }

    __syncthreads();
    float* pm = g_part_kx + ((size_t)b * NPARTS + part) * CQ * C;
#pragma unroll
    for (int i = 0; i < 4; i++)
#pragma unroll
        for (int j = 0; j < 3; j++)
            *(u64*)&pm[(wgrp + 8 * i) * C + pl + 64 * j] = macc[i][j];
    if (tid < 96) {
        float lo, hi; unpack2(xacc, lo, hi);
        float* px = g_part_xsum + ((size_t)b * NPARTS + part) * C;
        px[2 * tid] = lo; px[2 * tid + 1] = hi;
    }
    if (tid < 32) g_part_ksum[((size_t)b * NPARTS + part) * CQ + tid] = ksuml[tid];
}

// =============================================================================
// mid1: reduce partials (fixed order, float4)
// =============================================================================
__global__ void mid1_kernel()
{
    const int MAT4 = BATCH * CQ * C / 4;
    const int XS4  = BATCH * C / 4;
    const int KS4  = BATCH * CQ / 4;
    int idx = blockIdx.x * blockDim.x + threadIdx.x;
    if (idx < MAT4) {
        int i4 = idx * 4;
        int bb = i4 / (CQ * C), r = i4 % (CQ * C);
        const float* p = g_part_kx + (size_t)bb * NPARTS * CQ * C + r;
        float4 a = make_float4(0.f, 0.f, 0.f, 0.f);
#pragma unroll 8
        for (int q = 0; q < NPARTS; q++) {
            float4 v = *(const float4*)&p[(size_t)q * CQ * C];
            a.x += v.x; a.y += v.y; a.z += v.z; a.w += v.w;
        }
        *(float4*)&g_kx[i4] = a;
    } else if (idx < MAT4 + XS4) {
        int i4 = (idx - MAT4) * 4;
        int bb = i4 / C, r = i4 % C;
        const float* p = g_part_xsum + (size_t)bb * NPARTS * C + r;
        float4 a = make_float4(0.f, 0.f, 0.f, 0.f);
#pragma unroll 8
        for (int q = 0; q < NPARTS; q++) {
            float4 v = *(const float4*)&p[q * C];
            a.x += v.x; a.y += v.y; a.z += v.z; a.w += v.w;
        }
        *(float4*)&g_xsum[i4] = a;
    } else if (idx < MAT4 + XS4 + KS4) {
        int i4 = (idx - MAT4 - XS4) * 4;
        int bb = i4 / CQ, r = i4 % CQ;
        const float* p = g_part_ksum + (size_t)bb * NPARTS * CQ + r;
        float4 a = make_float4(0.f, 0.f, 0.f, 0.f);
#pragma unroll 8
        for (int q = 0; q < NPARTS; q++) {
            float4 v = *(const float4*)&p[q * CQ];
            a.x += v.x; a.y += v.y; a.z += v.z; a.w += v.w;
        }
        *(float4*)&g_ksum[i4] = a;
    }
}

// =============================================================================
// mid2: matrix = KX·Wv^T + ksum·bv^T ; vsum = Wv·xsum + N·bv
// =============================================================================
__global__ __launch_bounds__(256)
void mid2_kernel(const float* __restrict__ Wv, const float* __restrict__ bv)
{
    __shared__ float kxs[32 * 193];
    __shared__ float wvs[24 * 193];
    __shared__ float xsum_s[192];
    __shared__ float ksum_s[32];
    const int tid = threadIdx.x;
    const int b = blockIdx.x >> 3;
    const int c0 = (blockIdx.x & 7) * 24;

#pragma unroll
    for (int i = 0; i < 24; i++) {
        int idx = tid + 256 * i;
        int m = idx / 192, d = idx - m * 192;
        kxs[m * 193 + d] = g_kx[b * (CQ * C) + idx];
    }
#pragma unroll
    for (int i = 0; i < 18; i++) {
        int idx = tid + 256 * i;
        int r = idx / 192, d = idx - r * 192;
        wvs[r * 193 + d] = Wv[(size_t)(c0 + r) * C + d];
    }
    if (tid < 192) xsum_s[tid] = g_xsum[b * C + tid];
    if (tid < 32)  ksum_s[tid] = g_ksum[b * CQ + tid];
    __syncthreads();

#pragma unroll
    for (int e = 0; e < 3; e++) {
        int o = tid + 256 * e;
        int m = o / 24, c = o - m * 24;
        float acc = ksum_s[m] * bv[c0 + c];
#pragma unroll 8
        for (int d = 0; d < 192; d++)
            acc = fmaf(kxs[m * 193 + d], wvs[c * 193 + d], acc);
        g_mat[b * (CQ * C) + m * C + c0 + c] = acc;
    }
    if (tid < 24) {
        float acc = (float)NPIX * bv[c0 + tid];
#pragma unroll 8
        for (int d = 0; d < 192; d++)
            acc = fmaf(wvs[tid * 193 + d], xsum_s[d], acc);
        g_vsum[b * C + c0 + tid] = acc;
    }
}

// =============================================================================
// Pass 2: pure streaming GEMM — unchanged structure (measured 59.6 us)
// =============================================================================
__global__ __launch_bounds__(256, 2)
void pass2_kernel(const float* __restrict__ gamma, float* __restrict__ out)
{
    __shared__ float mats[32 * 192];
    __shared__ float qns[32 * 64];
    __shared__ float ksum_s[32];
    __shared__ float vsum_s[192];

    const int tid  = threadIdx.x;
    const int b    = blockIdx.y;
    const int part = blockIdx.x;
    const int cg   = tid >> 4;
    const int qd   = 4 * (tid & 15);
    const float gm = gamma[0];

#pragma unroll
    for (int i = 0; i < 24; i++)
        mats[tid + 256 * i] = g_mat[(size_t)b * CQ * C + tid + 256 * i];
    if (tid < 32)  ksum_s[tid] = g_ksum[b * CQ + tid] + 1e-6f;
    if (tid < 192) vsum_s[tid] = g_vsum[b * C + tid];

    const float* qnb = g_qn + (size_t)b * CQ * NPIX;
    float* outb = out + (size_t)b * C * NPIX;

    for (int s = 0; s < NSUBT; s++) {
        const int n0 = part * TILE + s * SUB;
        __syncthreads();   // A

#pragma unroll
        for (int i = 0; i < 2; i++) {
            int idx = tid + 256 * i;
            int m = idx >> 4, q = idx & 15;
            *(float4*)&qns[m * 64 + 4 * q] =
                *(const float4*)&qnb[(size_t)m * NPIX + n0 + 4 * q];
        }
        __syncthreads();   // B

        u64 sd0 = 0ull, sd1 = 0ull;
#pragma unroll 8
        for (int m = 0; m < CQ; m++) {
            ulonglong2 qv = *(const ulonglong2*)&qns[m * 64 + qd];
            u64 ks = pack2dup(ksum_s[m]);
            sd0 = ffma2(qv.x, ks, sd0);
            sd1 = ffma2(qv.y, ks, sd1);
        }
        float t0, t1, t2, t3;
        unpack2(sd0, t0, t1); unpack2(sd1, t2, t3);
        t0 = 1.0f / ((float)NPIX + t0); t1 = 1.0f / ((float)NPIX + t1);
        t2 = 1.0f / ((float)NPIX + t2); t3 = 1.0f / ((float)NPIX + t3);

        u64 oacc[4][6];
#pragma unroll
        for (int e = 0; e < 6; e++) {
            u64 vp = *(const u64*)&vsum_s[cg * 12 + 2 * e];
            oacc[0][e] = vp; oacc[1][e] = vp; oacc[2][e] = vp; oacc[3][e] = vp;
        }
#pragma unroll 4
        for (int m = 0; m < CQ; m++) {
            float4 qv = *(const float4*)&qns[m * 64 + qd];
            u64 q0 = pack2dup(qv.x), q1 = pack2dup(qv.y);
            u64 q2 = pack2dup(qv.z), q3 = pack2dup(qv.w);
#pragma unroll
            for (int j = 0; j < 3; j++) {
                ulonglong2 wv =
                    *(const ulonglong2*)&mats[m * 192 + cg * 12 + 4 * j];
                oacc[0][2*j]   = ffma2(wv.x, q0, oacc[0][2*j]);
                oacc[1][2*j]   = ffma2(wv.x, q1, oacc[1][2*j]);
                oacc[2][2*j]   = ffma2(wv.x, q2, oacc[2][2*j]);
                oacc[3][2*j]   = ffma2(wv.x, q3, oacc[3][2*j]);
                oacc[0][2*j+1] = ffma2(wv.y, q0, oacc[0][2*j+1]);
                oacc[1][2*j+1] = ffma2(wv.y, q1, oacc[1][2*j+1]);
                oacc[2][2*j+1] = ffma2(wv.y, q2, oacc[2][2*j+1]);
                oacc[3][2*j+1] = ffma2(wv.y, q3, oacc[3][2*j+1]);
            }
        }
        {
            u64 g0 = pack2dup(gm * t0), g1 = pack2dup(gm * t1);
            u64 g2 = pack2dup(gm * t2), g3 = pack2dup(gm * t3);
#pragma unroll
            for (int e = 0; e < 6; e++) {
                u64 o0 = fmul2(oacc[0][e], g0);
                u64 o1 = fmul2(oacc[1][e], g1);
                u64 o2 = fmul2(oacc[2][e], g2);
                u64 o3 = fmul2(oacc[3][e], g3);
                float l0, h0, l1, h1, l2, h2, l3, h3;
                unpack2(o0, l0, h0); unpack2(o1, l1, h1);
                unpack2(o2, l2, h2); unpack2(o3, l3, h3);
                const int c = cg * 12 + 2 * e;
                *(float4*)&outb[(size_t)c * NPIX + n0 + qd] =
                    make_float4(l0, l1, l2, l3);
                *(float4*)&outb[(size_t)(c + 1) * NPIX + n0 + qd] =
                    make_float4(h0, h1, h2, h3);
            }
        }
    }
}

// =============================================================================
extern "C" void kernel_launch(void* const* d_in, const int* in_sizes, int n_in,
                              void* d_out, int out_size)
{
    const float* x     = (const float*)d_in[0];
    const float* x1    = (const float*)d_in[1];
    const float* Wq    = (const float*)d_in[2];
    const float* bq    = (const float*)d_in[3];
    const float* Wk    = (const float*)d_in[4];
    const float* bk    = (const float*)d_in[5];
    const float* Wv    = (const float*)d_in[6];
    const float* bv    = (const float*)d_in[7];
    const float* gamma = (const float*)d_in[8];
    float* out = (float*)d_out;

    cudaFuncSetAttribute(pass1_kernel,
                         cudaFuncAttributeMaxDynamicSharedMemorySize, SMEM1_BYTES);

    dim3 grid(NPARTS, BATCH);
    pass1_kernel<<<grid, 256, SMEM1_BYTES>>>(x, x1, Wk, bk, Wq, bq);

    const int R4 = BATCH * CQ * C / 4 + BATCH * C / 4 + BATCH * CQ / 4;
    mid1_kernel<<<(R4 + 255) / 256, 256>>>();
    mid2_kernel<<<64, 256>>>(Wv, bv);

    pass2_kernel<<<grid, 256>>>(gamma, out);
}

// round 15
// speedup vs baseline: 1.5809x; 1.0039x over previous
#include <cuda_runtime.h>
#include <cstdint>

#define BATCH 8
#define C     192
#define CQ    32
#define NPIX  16384
#define SUB   64
#define NSUBT 2
#define TILE  (SUB*NSUBT)     // 128
#define NPARTS (NPIX/TILE)    // 128
// pass2 tiling (independent)
#define NSUBT2 1
#define TILE2  (SUB*NSUBT2)   // 64
#define NPARTS2 (NPIX/TILE2)  // 256

typedef unsigned long long u64;

// ---------------- deterministic scratch ----------------
__device__ float g_part_kx  [BATCH*NPARTS*CQ*C];   // 25.2 MB
__device__ float g_part_xsum[BATCH*NPARTS*C];
__device__ float g_part_ksum[BATCH*NPARTS*CQ];
__device__ float g_kx  [BATCH*CQ*C];
__device__ float g_xsum[BATCH*C];
__device__ float g_ksum[BATCH*CQ];
__device__ float g_mat [BATCH*CQ*C];
__device__ float g_vsum[BATCH*C];
__device__ float g_qn  [BATCH*CQ*NPIX];   // 16.8 MB: normalized Q

// ---------------- packed f32x2 helpers ----------------
__device__ __forceinline__ u64 pack2dup(float x) {
    u64 r; asm("mov.b64 %0, {%1, %1};" : "=l"(r) : "f"(x)); return r;
}
__device__ __forceinline__ u64 pack2(float a, float b) {
    u64 r; asm("mov.b64 %0, {%1, %2};" : "=l"(r) : "f"(a), "f"(b)); return r;
}
__device__ __forceinline__ void unpack2(u64 v, float& lo, float& hi) {
    asm("mov.b64 {%0, %1}, %2;" : "=f"(lo), "=f"(hi) : "l"(v));
}
__device__ __forceinline__ u64 ffma2(u64 a, u64 b, u64 c) {
    u64 d; asm("fma.rn.f32x2 %0, %1, %2, %3;" : "=l"(d) : "l"(a), "l"(b), "l"(c));
    return d;
}
__device__ __forceinline__ u64 fmul2(u64 a, u64 b) {
    u64 d; asm("mul.rn.f32x2 %0, %1, %2;" : "=l"(d) : "l"(a), "l"(b)); return d;
}
__device__ __forceinline__ u64 fadd2(u64 a, u64 b) {
    u64 d; asm("add.rn.f32x2 %0, %1, %2;" : "=l"(d) : "l"(a), "l"(b)); return d;
}

// ---------------- smem layout (pass1, float offsets) ----------------
#define P1_BUF0   0        // x1 [192][64] then xt [64][194] -> 12416
#define P1_WK     12416    // [32][196] = 6272
#define P1_WQ     18688    // [32][196] = 6272
#define P1_KN     24960    // [32][64]  = 2048
#define P1_KSQ    27008    // [8][64]   = 512
#define P1_QSQ    27520    // [8][64]   = 512
#define P1_INVN   28032    // [64]
#define P1_INVQ   28096    // [64]
#define P1_WKP    28160    // [32]
#define P1_KSUML  28192    // [32]
#define P1_TOT    28224
#define SMEM1_BYTES (P1_TOT*4)   // 112896 B; 2 CTAs/SM

// =============================================================================
// Pass 1: K-proj (lower half) + Q-proj (upper half) with x prefetch overlap;
//         Kn, KX = Kn·x^T, ksum, xsum; Qn -> g_qn.  Balanced phases.
// =============================================================================
__global__ __launch_bounds__(256, 2)
void pass1_kernel(const float* __restrict__ x, const float* __restrict__ x1,
                  const float* __restrict__ Wk, const float* __restrict__ bk,
                  const float* __restrict__ Wq, const float* __restrict__ bq)
{
    extern __shared__ float sm[];
    float* buf0  = sm + P1_BUF0;
    float* wk    = sm + P1_WK;
    float* wq    = sm + P1_WQ;
    float* kn    = sm + P1_KN;
    float* ksq   = sm + P1_KSQ;
    float* qsq   = sm + P1_QSQ;
    float* invn  = sm + P1_INVN;
    float* invq  = sm + P1_INVQ;
    float* wkp   = sm + P1_WKP;
    float* ksuml = sm + P1_KSUML;

    const int tid  = threadIdx.x;
    const int lane = tid & 31;
    const int wgrp = tid >> 5;
    const int b    = blockIdx.y;
    const int part = blockIdx.x;
    const int pl   = 2 * lane;
    const int ph   = tid >> 7;          // 0 = K half, 1 = Q half
    const int u    = tid & 127;
    const int mg   = u >> 4;            // m-group (4 m)
    const int qd   = 4 * (u & 15);      // px quad

    // stage both weight matrices, stride 196 (16B-aligned rows)
#pragma unroll
    for (int i = 0; i < 24; i++) {
        int idx = tid + 256 * i;
        int m = idx / 192, k = idx - m * 192;
        wk[m * 196 + k] = Wk[idx];
        wq[m * 196 + k] = Wq[idx];
    }
    if (tid < 32) ksuml[tid] = 0.f;

    float br[4];
#pragma unroll
    for (int mi = 0; mi < 4; mi++)
        br[mi] = ph ? bq[mg * 4 + mi] : bk[mg * 4 + mi];
    const float* wsel = ph ? wq : wk;
    float* sqdst = ph ? qsq : ksq;

    u64 macc[4][3];
#pragma unroll
    for (int i = 0; i < 4; i++)
#pragma unroll
        for (int j = 0; j < 3; j++) macc[i][j] = 0ull;
    u64 xacc = 0ull;   // xsum partial: Q-half threads 128..223, ch pair 2*(tid-128)

    const float* x1b = x1 + (size_t)b * C * NPIX;
    const float* xb  = x  + (size_t)b * C * NPIX;
    float* qnb = g_qn + (size_t)b * CQ * NPIX;

    for (int s = 0; s < NSUBT; s++) {
        const int n0 = part * TILE + s * SUB;
        __syncthreads();   // A: buf0/kn reuse guard

        // ---- stage x1 -> buf0[c][t] stride 64 (all threads) ----
#pragma unroll
        for (int i = 0; i < 12; i++) {
            int idx = tid + 256 * i;
            int c = idx >> 4, q = idx & 15;
            *(float4*)&buf0[c * 64 + 4 * q] =
                *(const float4*)&x1b[(size_t)c * NPIX + n0 + 4 * q];
        }
        __syncthreads();   // B

        // ---- PREFETCH x first half (channels 0..95) — overlaps the proj ----
        float4 xr[6];
#pragma unroll
        for (int i = 0; i < 6; i++) {
            int idx = tid + 256 * i;
            int c = idx >> 4, q = idx & 15;
            xr[i] = *(const float4*)&xb[(size_t)c * NPIX + n0 + 4 * q];
        }

        // ---- projection (K on lower half, Q on upper half) ----
        u64 acc[4][2];
#pragma unroll
        for (int mi = 0; mi < 4; mi++) {
            u64 bb = pack2dup(br[mi]);
            acc[mi][0] = bb; acc[mi][1] = bb;
        }
#pragma unroll 3
        for (int k = 0; k < C; k += 4) {
            ulonglong2 xA = *(const ulonglong2*)&buf0[k * 64 + qd];
            ulonglong2 xC = *(const ulonglong2*)&buf0[(k + 1) * 64 + qd];
            ulonglong2 xE = *(const ulonglong2*)&buf0[(k + 2) * 64 + qd];
            ulonglong2 xG = *(const ulonglong2*)&buf0[(k + 3) * 64 + qd];
#pragma unroll
            for (int mi = 0; mi < 4; mi++) {
                float4 w = *(const float4*)&wsel[(mg * 4 + mi) * 196 + k];
                u64 w0 = pack2dup(w.x), w1 = pack2dup(w.y);
                u64 w2 = pack2dup(w.z), w3 = pack2dup(w.w);
                acc[mi][0] = ffma2(xA.x, w0, acc[mi][0]);
                acc[mi][1] = ffma2(xA.y, w0, acc[mi][1]);
                acc[mi][0] = ffma2(xC.x, w1, acc[mi][0]);
                acc[mi][1] = ffma2(xC.y, w1, acc[mi][1]);
                acc[mi][0] = ffma2(xE.x, w2, acc[mi][0]);
                acc[mi][1] = ffma2(xE.y, w2, acc[mi][1]);
                acc[mi][0] = ffma2(xG.x, w3, acc[mi][0]);
                acc[mi][1] = ffma2(xG.y, w3, acc[mi][1]);
            }
        }
        {
            u64 sq0 = fmul2(acc[0][0], acc[0][0]);
            u64 sq1 = fmul2(acc[0][1], acc[0][1]);
#pragma unroll
            for (int mi = 1; mi < 4; mi++) {
                sq0 = ffma2(acc[mi][0], acc[mi][0], sq0);
                sq1 = ffma2(acc[mi][1], acc[mi][1], sq1);
            }
            *(u64*)&sqdst[mg * 64 + qd]     = sq0;
            *(u64*)&sqdst[mg * 64 + qd + 2] = sq1;
        }
        __syncthreads();   // C: proj reads done, ksq+qsq ready

        // balanced reductions: K-half lower warps do invn, Q-half lower warps invq
        if (tid < 64) {
            float tot = 0.f;
#pragma unroll
            for (int g = 0; g < 8; g++) tot += ksq[g * 64 + tid];
            invn[tid] = rsqrtf(tot);
        } else if (tid >= 128 && tid < 192) {
            const int t = tid - 128;
            float tot = 0.f;
#pragma unroll
            for (int g = 0; g < 8; g++) tot += qsq[g * 64 + t];
            invq[t] = rsqrtf(tot);
        }
        // ---- issue second-half x loads (in flight during xr stores) ----
        float4 xr2[6];
#pragma unroll
        for (int i = 0; i < 6; i++) {
            int idx = tid + 256 * (i + 6);
            int c = idx >> 4, q = idx & 15;
            xr2[i] = *(const float4*)&xb[(size_t)c * NPIX + n0 + 4 * q];
        }
        // ---- store prefetched first half transposed -> xt[t][194] ----
#pragma unroll
        for (int i = 0; i < 6; i++) {
            int idx = tid + 256 * i;
            int c = idx >> 4, q = idx & 15;
            buf0[(4 * q)     * 194 + c] = xr[i].x;
            buf0[(4 * q + 1) * 194 + c] = xr[i].y;
            buf0[(4 * q + 2) * 194 + c] = xr[i].z;
            buf0[(4 * q + 3) * 194 + c] = xr[i].w;
        }
        // ---- store second half ----
#pragma unroll
        for (int i = 0; i < 6; i++) {
            int idx = tid + 256 * (i + 6);
            int c = idx >> 4, q = idx & 15;
            buf0[(4 * q)     * 194 + c] = xr2[i].x;
            buf0[(4 * q + 1) * 194 + c] = xr2[i].y;
            buf0[(4 * q + 2) * 194 + c] = xr2[i].z;
            buf0[(4 * q + 3) * 194 + c] = xr2[i].w;
        }
        __syncthreads();   // D: invn/invq + xt ready

        if (ph == 0) {
            // ---- kn = K*inv (float4 store), ksum via 16-lane shfl ----
            float4 iv = *(const float4*)&invn[qd];
            u64 iv0 = pack2(iv.x, iv.y), iv1 = pack2(iv.z, iv.w);
            float ksump[4];
#pragma unroll
            for (int mi = 0; mi < 4; mi++) {
                u64 k0 = fmul2(acc[mi][0], iv0);
                u64 k1 = fmul2(acc[mi][1], iv1);
                float a0, a1, a2, a3;
                unpack2(k0, a0, a1); unpack2(k1, a2, a3);
                *(float4*)&kn[(mg * 4 + mi) * 64 + qd] =
                    make_float4(a0, a1, a2, a3);
                ksump[mi] = (a0 + a1) + (a2 + a3);
            }
#pragma unroll
            for (int off = 8; off; off >>= 1)
#pragma unroll
                for (int mi = 0; mi < 4; mi++)
                    ksump[mi] += __shfl_down_sync(0xffffffffu, ksump[mi], off, 16);
            if ((u & 15) == 0)
#pragma unroll
                for (int mi = 0; mi < 4; mi++) wkp[mg * 4 + mi] = ksump[mi];
        } else {
            // ---- qn = Q*invq -> g_qn (STG.128 per m) ----
            float4 iv = *(const float4*)&invq[qd];
            u64 iv0 = pack2(iv.x, iv.y), iv1 = pack2(iv.z, iv.w);
#pragma unroll
            for (int mi = 0; mi < 4; mi++) {
                u64 q0 = fmul2(acc[mi][0], iv0);
                u64 q1 = fmul2(acc[mi][1], iv1);
                float a0, a1, a2, a3;
                unpack2(q0, a0, a1); unpack2(q1, a2, a3);
                *(float4*)&qnb[(size_t)(mg * 4 + mi) * NPIX + n0 + qd] =
                    make_float4(a0, a1, a2, a3);
            }
        }
        __syncthreads();   // E: kn + wkp + xt ready

        if (tid < 32) ksuml[tid] += wkp[tid];

        // ---- xsum partial (Q-half threads 128..223) ----
        if (ph == 1 && u < 96) {
            u64 sv = 0ull;
#pragma unroll 8
            for (int t = 0; t < SUB; t++)
                sv = fadd2(sv, *(const u64*)&buf0[t * 194 + 2 * u]);
            xacc = fadd2(xacc, sv);
        }

        // ---- KX += kn·x^T (t-block-4, broadcast kn LDS.128) ----
#pragma unroll 4
        for (int tb = 0; tb < 16; tb++) {
            const int t0 = 4 * tb;
            float4 kd[4];
#pragma unroll
            for (int i = 0; i < 4; i++)
                kd[i] = *(const float4*)&kn[(wgrp + 8 * i) * 64 + t0];
#pragma unroll
            for (int tt = 0; tt < 4; tt++) {
                u64 x2[3];
#pragma unroll
                for (int j = 0; j < 3; j++)
                    x2[j] = *(const u64*)&buf0[(t0 + tt) * 194 + pl + 64 * j];
                const float* kf0 = (const float*)&kd[0];
                const float* kf1 = (const float*)&kd[1];
                const float* kf2 = (const float*)&kd[2];
                const float* kf3 = (const float*)&kd[3];
                u64 kd0 = pack2dup(kf0[tt]);
                u64 kd1 = pack2dup(kf1[tt]);
                u64 kd2 = pack2dup(kf2[tt]);
                u64 kd3 = pack2dup(kf3[tt]);
#pragma unroll
                for (int j = 0; j < 3; j++) {
                    macc[0][j] = ffma2(kd0, x2[j], macc[0][j]);
                    macc[1][j] = ffma2(kd1, x2[j], macc[1][j]);
                    macc[2][j] = ffma2(kd2, x2[j], macc[2][j]);
                    macc[3][j] = ffma2(kd3, x2[j], macc[3][j]);
                }
            }
        }
    }

    __syncthreads();
    float* pm = g_part_kx + ((size_t)b * NPARTS + part) * CQ * C;
#pragma unroll
    for (int i = 0; i < 4; i++)
#pragma unroll
        for (int j = 0; j < 3; j++)
            *(u64*)&pm[(wgrp + 8 * i) * C + pl + 64 * j] = macc[i][j];
    if (ph == 1 && u < 96) {
        float lo, hi; unpack2(xacc, lo, hi);
        float* px = g_part_xsum + ((size_t)b * NPARTS + part) * C;
        px[2 * u] = lo; px[2 * u + 1] = hi;
    }
    if (tid < 32) g_part_ksum[((size_t)b * NPARTS + part) * CQ + tid] = ksuml[tid];
}

// =============================================================================
// mid1: reduce partials (fixed order, float4)
// =============================================================================
__global__ void mid1_kernel()
{
    const int MAT4 = BATCH * CQ * C / 4;
    const int XS4  = BATCH * C / 4;
    const int KS4  = BATCH * CQ / 4;
    int idx = blockIdx.x * blockDim.x + threadIdx.x;
    if (idx < MAT4) {
        int i4 = idx * 4;
        int bb = i4 / (CQ * C), r = i4 % (CQ * C);
        const float* p = g_part_kx + (size_t)bb * NPARTS * CQ * C + r;
        float4 a = make_float4(0.f, 0.f, 0.f, 0.f);
#pragma unroll 8
        for (int q = 0; q < NPARTS; q++) {
            float4 v = *(const float4*)&p[(size_t)q * CQ * C];
            a.x += v.x; a.y += v.y; a.z += v.z; a.w += v.w;
        }
        *(float4*)&g_kx[i4] = a;
    } else if (idx < MAT4 + XS4) {
        int i4 = (idx - MAT4) * 4;
        int bb = i4 / C, r = i4 % C;
        const float* p = g_part_xsum + (size_t)bb * NPARTS * C + r;
        float4 a = make_float4(0.f, 0.f, 0.f, 0.f);
#pragma unroll 8
        for (int q = 0; q < NPARTS; q++) {
            float4 v = *(const float4*)&p[q * C];
            a.x += v.x; a.y += v.y; a.z += v.z; a.w += v.w;
        }
        *(float4*)&g_xsum[i4] = a;
    } else if (idx < MAT4 + XS4 + KS4) {
        int i4 = (idx - MAT4 - XS4) * 4;
        int bb = i4 / CQ, r = i4 % CQ;
        const float* p = g_part_ksum + (size_t)bb * NPARTS * CQ + r;
        float4 a = make_float4(0.f, 0.f, 0.f, 0.f);
#pragma unroll 8
        for (int q = 0; q < NPARTS; q++) {
            float4 v = *(const float4*)&p[q * CQ];
            a.x += v.x; a.y += v.y; a.z += v.z; a.w += v.w;
        }
        *(float4*)&g_ksum[i4] = a;
    }
}

// =============================================================================
// mid2: matrix = KX·Wv^T + ksum·bv^T ; vsum = Wv·xsum + N·bv
// =============================================================================
__global__ __launch_bounds__(256)
void mid2_kernel(const float* __restrict__ Wv, const float* __restrict__ bv)
{
    __shared__ float kxs[32 * 193];
    __shared__ float wvs[24 * 193];
    __shared__ float xsum_s[192];
    __shared__ float ksum_s[32];
    const int tid = threadIdx.x;
    const int b = blockIdx.x >> 3;
    const int c0 = (blockIdx.x & 7) * 24;

#pragma unroll
    for (int i = 0; i < 24; i++) {
        int idx = tid + 256 * i;
        int m = idx / 192, d = idx - m * 192;
        kxs[m * 193 + d] = g_kx[b * (CQ * C) + idx];
    }
#pragma unroll
    for (int i = 0; i < 18; i++) {
        int idx = tid + 256 * i;
        int r = idx / 192, d = idx - r * 192;
        wvs[r * 193 + d] = Wv[(size_t)(c0 + r) * C + d];
    }
    if (tid < 192) xsum_s[tid] = g_xsum[b * C + tid];
    if (tid < 32)  ksum_s[tid] = g_ksum[b * CQ + tid];
    __syncthreads();

#pragma unroll
    for (int e = 0; e < 3; e++) {
        int o = tid + 256 * e;
        int m = o / 24, c = o - m * 24;
        float acc = ksum_s[m] * bv[c0 + c];
#pragma unroll 8
        for (int d = 0; d < 192; d++)
            acc = fmaf(kxs[m * 193 + d], wvs[c * 193 + d], acc);
        g_mat[b * (CQ * C) + m * C + c0 + c] = acc;
    }
    if (tid < 24) {
        float acc = (float)NPIX * bv[c0 + tid];
#pragma unroll 8
        for (int d = 0; d < 192; d++)
            acc = fmaf(wvs[tid * 193 + d], xsum_s[d], acc);
        g_vsum[b * C + c0 + tid] = acc;
    }
}

// =============================================================================
// Pass 2: pure streaming GEMM, TILE2=64 (fine waves)
// =============================================================================
__global__ __launch_bounds__(256, 2)
void pass2_kernel(const float* __restrict__ gamma, float* __restrict__ out)
{
    __shared__ float mats[32 * 192];
    __shared__ float qns[32 * 64];
    __shared__ float ksum_s[32];
    __shared__ float vsum_s[192];

    const int tid  = threadIdx.x;
    const int b    = blockIdx.y;
    const int part = blockIdx.x;
    const int cg   = tid >> 4;
    const int qd   = 4 * (tid & 15);
    const float gm = gamma[0];

#pragma unroll
    for (int i = 0; i < 24; i++)
        mats[tid + 256 * i] = g_mat[(size_t)b * CQ * C + tid + 256 * i];
    if (tid < 32)  ksum_s[tid] = g_ksum[b * CQ + tid] + 1e-6f;
    if (tid < 192) vsum_s[tid] = g_vsum[b * C + tid];

    const float* qnb = g_qn + (size_t)b * CQ * NPIX;
    float* outb = out + (size_t)b * C * NPIX;

    for (int s = 0; s < NSUBT2; s++) {
        const int n0 = part * TILE2 + s * SUB;
        __syncthreads();   // A

#pragma unroll
        for (int i = 0; i < 2; i++) {
            int idx = tid + 256 * i;
            int m = idx >> 4, q = idx & 15;
            *(float4*)&qns[m * 64 + 4 * q] =
                *(const float4*)&qnb[(size_t)m * NPIX + n0 + 4 * q];
        }
        __syncthreads();   // B

        u64 sd0 = 0ull, sd1 = 0ull;
#pragma unroll 8
        for (int m = 0; m < CQ; m++) {
            ulonglong2 qv = *(const ulonglong2*)&qns[m * 64 + qd];
            u64 ks = pack2dup(ksum_s[m]);
            sd0 = ffma2(qv.x, ks, sd0);
            sd1 = ffma2(qv.y, ks, sd1);
        }
        float t0, t1, t2, t3;
        unpack2(sd0, t0, t1); unpack2(sd1, t2, t3);
        t0 = 1.0f / ((float)NPIX + t0); t1 = 1.0f / ((float)NPIX + t1);
        t2 = 1.0f / ((float)NPIX + t2); t3 = 1.0f / ((float)NPIX + t3);

        u64 oacc[4][6];
#pragma unroll
        for (int e = 0; e < 6; e++) {
            u64 vp = *(const u64*)&vsum_s[cg * 12 + 2 * e];
            oacc[0][e] = vp; oacc[1][e] = vp; oacc[2][e] = vp; oacc[3][e] = vp;
        }
#pragma unroll 4
        for (int m = 0; m < CQ; m++) {
            float4 qv = *(const float4*)&qns[m * 64 + qd];
            u64 q0 = pack2dup(qv.x), q1 = pack2dup(qv.y);
            u64 q2 = pack2dup(qv.z), q3 = pack2dup(qv.w);
#pragma unroll
            for (int j = 0; j < 3; j++) {
                ulonglong2 wv =
                    *(const ulonglong2*)&mats[m * 192 + cg * 12 + 4 * j];
                oacc[0][2*j]   = ffma2(wv.x, q0, oacc[0][2*j]);
                oacc[1][2*j]   = ffma2(wv.x, q1, oacc[1][2*j]);
                oacc[2][2*j]   = ffma2(wv.x, q2, oacc[2][2*j]);
                oacc[3][2*j]   = ffma2(wv.x, q3, oacc[3][2*j]);
                oacc[0][2*j+1] = ffma2(wv.y, q0, oacc[0][2*j+1]);
                oacc[1][2*j+1] = ffma2(wv.y, q1, oacc[1][2*j+1]);
                oacc[2][2*j+1] = ffma2(wv.y, q2, oacc[2][2*j+1]);
                oacc[3][2*j+1] = ffma2(wv.y, q3, oacc[3][2*j+1]);
            }
        }
        {
            u64 g0 = pack2dup(gm * t0), g1 = pack2dup(gm * t1);
            u64 g2 = pack2dup(gm * t2), g3 = pack2dup(gm * t3);
#pragma unroll
            for (int e = 0; e < 6; e++) {
                u64 o0 = fmul2(oacc[0][e], g0);
                u64 o1 = fmul2(oacc[1][e], g1);
                u64 o2 = fmul2(oacc[2][e], g2);
                u64 o3 = fmul2(oacc[3][e], g3);
                float l0, h0, l1, h1, l2, h2, l3, h3;
                unpack2(o0, l0, h0); unpack2(o1, l1, h1);
                unpack2(o2, l2, h2); unpack2(o3, l3, h3);
                const int c = cg * 12 + 2 * e;
                *(float4*)&outb[(size_t)c * NPIX + n0 + qd] =
                    make_float4(l0, l1, l2, l3);
                *(float4*)&outb[(size_t)(c + 1) * NPIX + n0 + qd] =
                    make_float4(h0, h1, h2, h3);
            }
        }
    }
}

// =============================================================================
extern "C" void kernel_launch(void* const* d_in, const int* in_sizes, int n_in,
                              void* d_out, int out_size)
{
    const float* x     = (const float*)d_in[0];
    const float* x1    = (const float*)d_in[1];
    const float* Wq    = (const float*)d_in[2];
    const float* bq    = (const float*)d_in[3];
    const float* Wk    = (const float*)d_in[4];
    const float* bk    = (const float*)d_in[5];
    const float* Wv    = (const float*)d_in[6];
    const float* bv    = (const float*)d_in[7];
    const float* gamma = (const float*)d_in[8];
    float* out = (float*)d_out;

    cudaFuncSetAttribute(pass1_kernel,
                         cudaFuncAttributeMaxDynamicSharedMemorySize, SMEM1_BYTES);

    dim3 grid1(NPARTS, BATCH);
    pass1_kernel<<<grid1, 256, SMEM1_BYTES>>>(x, x1, Wk, bk, Wq, bq);

    const int R4 = BATCH * CQ * C / 4 + BATCH * C / 4 + BATCH * CQ / 4;
    mid1_kernel<<<(R4 + 255) / 256, 256>>>();
    mid2_kernel<<<64, 256>>>(Wv, bv);

    dim3 grid2(NPARTS2, BATCH);
    pass2_kernel<<<grid2, 256>>>(gamma, out);
}